// round 10
// baseline (speedup 1.0000x reference)
#include <cuda_runtime.h>
#include <cstdint>

// HOG fused kernel R10: own pixel rows from GMEM registers + 8-row halo tile,
// shfl horizontal halos, 9-slot mod-9 histogram, paired overlapped RMW.
// x: (64,1,512,512) f32. out: (64, 9*64*64) f32.
// Block = (image n, cell-row cy) stripe, 256 threads: cell = t/4, sub = t%4 (2 rows).
// Tile rows (stripe-relative): {-1,1,2,3,4,5,6,8} -> tr 0..7. Thread sub reads
// tr_top = (sub==0?0:2s-1), tr_bot = (sub==3?7:2s+2). Col c -> 10*(c>>3)+(c&7)+4.

#define TS2 646

__device__ __forceinline__ uint32_t smem_u32(const void* p)
{
    uint32_t a;
    asm("{ .reg .u64 t; cvta.to.shared.u64 t, %1; cvt.u32.u64 %0, t; }"
        : "=r"(a) : "l"(p));
    return a;
}

__device__ __forceinline__ float setge(float a, float b)
{
    float r;
    asm("set.ge.f32.f32 %0, %1, %2;" : "=f"(r) : "f"(a), "f"(b));
    return r;
}

// 9-slot histogram bucket address; slot = |fa - (signs_differ ? 8 : 0)| = fl mod 9
__device__ __forceinline__ uint32_t hog_class(float gx, float gy, uint32_t hb, float& mag)
{
    float d2 = fmaf(gx, gx, gy * gy);
    asm("sqrt.approx.f32 %0, %1;" : "=f"(mag) : "f"(d2));

    float u = fabsf(gx), v = fabsf(gy);
    float fa = (setge(u, 0.36397023f * v) + setge(u, 0.83909963f * v))
             + (setge(u, 1.73205081f * v) + setge(u, 5.67128182f * v));  // 0..4

    uint32_t xo = __float_as_uint(gx) ^ __float_as_uint(gy);
    float cf8 = ((int)xo < 0) ? 8.0f : 0.0f;
    float m = fabsf(fa - cf8) + 12582912.0f;     // 0x4B400000 + slot (exact)
    return hb + (__float_as_uint(m) << 10);
}

__device__ __forceinline__ void hog_pair(uint32_t a0, float m0, uint32_t a1, float m1)
{
    float msum = m0 + m1;
    asm volatile(
        "{\n\t"
        ".reg .pred p;\n\t"
        ".reg .f32 t0, t1, v0;\n\t"
        "setp.ne.u32 p, %0, %1;\n\t"
        "selp.f32 v0, %2, %3, p;\n\t"
        "ld.shared.f32 t0, [%0];\n\t"
        "@p ld.shared.f32 t1, [%1];\n\t"
        "add.f32 t0, t0, v0;\n\t"
        "@p add.f32 t1, t1, %4;\n\t"
        "st.shared.f32 [%0], t0;\n\t"
        "@p st.shared.f32 [%1], t1;\n\t"
        "}"
        :: "r"(a0), "r"(a1), "f"(m0), "f"(msum), "f"(m1));
}

__device__ __forceinline__ void emit(uint32_t hb, float gx0, float gy0, float gx1, float gy1)
{
    float m0, m1;
    uint32_t q0 = hog_class(gx0, gy0, hb, m0);
    uint32_t q1 = hog_class(gx1, gy1, hb, m1);
    hog_pair(q0, m0, q1, m1);
}

__global__ __launch_bounds__(256, 5)
void hog_kernel(const float* __restrict__ x, float* __restrict__ out)
{
    __shared__ __align__(16) float tile[8 * TS2];
    __shared__ float hist[9 * 256];

    const int tid  = threadIdx.x;
    const int n    = blockIdx.x >> 6;
    const int cy   = blockIdx.x & 63;
    const int cell = tid >> 2;
    const int sub  = tid & 3;
    const int lane = tid & 31;
    const uint32_t hb = smem_u32(&hist[tid]);

#pragma unroll
    for (int b = 0; b < 9; ++b) hist[b * 256 + tid] = 0.0f;

    const float* img  = x + (size_t)n * (512 * 512);
    const int    row0 = cy * 8;

    // ---- cooperative halo-row tile load: rows {-1,1,2,3,4,5,6,8} ----
#pragma unroll
    for (int i = 0; i < 4; ++i) {
        int idx = tid + i * 256;          // 0..1023
        int r   = idx >> 7;               // tile row 0..7
        int k   = idx & 127;              // float4 in row
        int sr  = (r == 0) ? -1 : ((r == 7) ? 8 : r);
        int gr  = row0 + sr;
        float4 v = make_float4(0.f, 0.f, 0.f, 0.f);
        if ((unsigned)gr < 512u)
            v = *reinterpret_cast<const float4*>(img + (size_t)gr * 512 + k * 4);
        float* d = &tile[r * TS2 + 5 * k + 4 - (k & 1)];
        *reinterpret_cast<float2*>(d)     = make_float2(v.x, v.y);
        *reinterpret_cast<float2*>(d + 2) = make_float2(v.z, v.w);
    }
    if (tid < 8) { tile[tid * TS2 + 1] = 0.f; tile[tid * TS2 + 644] = 0.f; }

    // ---- own pixel rows (2s, 2s+1) straight to registers; always in-range ----
    const int c0  = cell * 8;
    const int rm  = row0 + 2 * sub;
    const float* pm = img + (size_t)rm * 512 + c0;
    const float* pn = pm + 512;
    float4 Lm = *reinterpret_cast<const float4*>(pm);
    float4 Rm = *reinterpret_cast<const float4*>(pm + 4);
    float4 Ln = *reinterpret_cast<const float4*>(pn);
    float4 Rn = *reinterpret_cast<const float4*>(pn + 4);

    // horizontal halos via shuffle (lane +-4 = neighbor cell, same sub)
    float lfm = __shfl_up_sync(0xffffffffu, Rm.w, 4);
    float lfn = __shfl_up_sync(0xffffffffu, Rn.w, 4);
    float rgm = __shfl_down_sync(0xffffffffu, Lm.x, 4);
    float rgn = __shfl_down_sync(0xffffffffu, Ln.x, 4);
    if (lane < 4) {
        lfm = (c0 > 0) ? pm[-1] : 0.f;
        lfn = (c0 > 0) ? pn[-1] : 0.f;
    }
    if (lane >= 28) {
        rgm = (c0 + 8 < 512) ? pm[8] : 0.f;
        rgn = (c0 + 8 < 512) ? pn[8] : 0.f;
    }
    __syncthreads();

    // row arrays (constant-indexed after unroll)
    float m[10], nn[10];
    m[0] = lfm; m[1] = Lm.x; m[2] = Lm.y; m[3] = Lm.z; m[4] = Lm.w;
    m[5] = Rm.x; m[6] = Rm.y; m[7] = Rm.z; m[8] = Rm.w; m[9] = rgm;
    nn[0] = lfn; nn[1] = Ln.x; nn[2] = Ln.y; nn[3] = Ln.z; nn[4] = Ln.w;
    nn[5] = Rn.x; nn[6] = Rn.y; nn[7] = Rn.z; nn[8] = Rn.w; nn[9] = rgn;

    // halo tile rows for this thread
    const int tr_top = (sub == 0) ? 0 : (2 * sub - 1);
    const int tr_bot = (sub == 3) ? 7 : (2 * sub + 2);
    const float* pt = &tile[tr_top * TS2 + 10 * cell];
    const float* pb = &tile[tr_bot * TS2 + 10 * cell];

    // ---- mainloop: col pairs; t (top halo) & b (bottom halo) streamed ----
    float lw = pt[1], lc = pb[1];
    float2 wp = *reinterpret_cast<const float2*>(pt + 4);
    float2 cp = *reinterpret_cast<const float2*>(pb + 4);

    float Am1 = lw + 2.f * m[0] + nn[0];
    float Bm1 = m[0] + 2.f * nn[0] + lc;
    float A0 = wp.x + 2.f * m[1] + nn[1], A1 = wp.y + 2.f * m[2] + nn[2];
    float B0 = m[1] + 2.f * nn[1] + cp.x, B1 = m[2] + 2.f * nn[2] + cp.y;

    // col 0
    emit(hb,
         Am1 - A1, (lw + 2.f * wp.x + wp.y) - (nn[0] + 2.f * nn[1] + nn[2]),
         Bm1 - B1, (m[0] + 2.f * m[1] + m[2]) - (lc + 2.f * cp.x + cp.y));

    float w0 = wp.x, w1 = wp.y, c0v = cp.x, c1v = cp.y;

#pragma unroll
    for (int k = 1; k < 4; ++k) {
        float2 wn2 = *reinterpret_cast<const float2*>(pt + 4 + 2 * k);
        float2 cn2 = *reinterpret_cast<const float2*>(pb + 4 + 2 * k);
        int j = 2 * k + 1;   // m/nn indices j, j+1
        float A2 = wn2.x + 2.f * m[j] + nn[j],         A3 = wn2.y + 2.f * m[j + 1] + nn[j + 1];
        float B2 = m[j] + 2.f * nn[j] + cn2.x,         B3 = m[j + 1] + 2.f * nn[j + 1] + cn2.y;

        // col 2k-1
        emit(hb,
             A0 - A2, (w0 + 2.f * w1 + wn2.x) - (nn[j - 2] + 2.f * nn[j - 1] + nn[j]),
             B0 - B2, (m[j - 2] + 2.f * m[j - 1] + m[j]) - (c0v + 2.f * c1v + cn2.x));
        // col 2k
        emit(hb,
             A1 - A3, (w1 + 2.f * wn2.x + wn2.y) - (nn[j - 1] + 2.f * nn[j] + nn[j + 1]),
             B1 - B3, (m[j - 1] + 2.f * m[j] + m[j + 1]) - (c1v + 2.f * cn2.x + cn2.y));

        w0 = wn2.x; w1 = wn2.y; c0v = cn2.x; c1v = cn2.y;
        A0 = A2; A1 = A3; B0 = B2; B1 = B3;
    }

    // col 7 with right halo (col 8)
    {
        float rw = pt[14], rc = pb[14];
        float A8 = rw + 2.f * m[9] + nn[9];
        float B8 = m[9] + 2.f * nn[9] + rc;
        emit(hb,
             A0 - A8, (w0 + 2.f * w1 + rw) - (nn[7] + 2.f * nn[8] + nn[9]),
             B0 - B8, (m[7] + 2.f * m[8] + m[9]) - (c0v + 2.f * c1v + rc));
    }

    asm volatile("" ::: "memory");   // order fold reads after asm RMWs

    // ---- fold: bin[b] = P9[b] + P9[(b+8)%9]; shuffle-reduce 4 subs; write ----
    float P[9];
#pragma unroll
    for (int s = 0; s < 9; ++s) P[s] = hist[s * 256 + tid];
    float bin[9];
#pragma unroll
    for (int b = 0; b < 9; ++b) bin[b] = P[b] + P[(b + 8) % 9];

#pragma unroll
    for (int b = 0; b < 9; ++b) {
        bin[b] += __shfl_xor_sync(0xffffffffu, bin[b], 1);
        bin[b] += __shfl_xor_sync(0xffffffffu, bin[b], 2);
    }

    if (sub == 0) {
        float* o = out + (size_t)n * 36864 + cy * 64 + cell;
#pragma unroll
        for (int b = 0; b < 9; ++b)
            o[(size_t)b * 4096] = bin[b] * 0.015625f;   // 1/64
    }
}

extern "C" void kernel_launch(void* const* d_in, const int* in_sizes, int n_in,
                              void* d_out, int out_size)
{
    const float* x = (const float*)d_in[0];
    float* out = (float*)d_out;
    (void)in_sizes; (void)n_in; (void)out_size;
    hog_kernel<<<4096, 256>>>(x, out);
}

// round 12
// speedup vs baseline: 1.0621x; 1.0621x over previous
#include <cuda_runtime.h>
#include <cstdint>

// HOG fused kernel R11: R9 body + no-halo-dup tile layout (col 8c+j -> 12c+j+8)
// + cp.async.cg tile fill. 9-slot mod-9 histogram, paired overlapped RMW.
// x: (64,1,512,512) f32. out: (64, 9*64*64) f32.
// Block = (image n, cell-row cy) stripe, 256 threads: cell = t/4, sub = t%4 (2 rows).
// Window for cell c: left halo [12c+3], data [12c+8..15], right halo [12c+20]
// (halos are the neighbor cells' own edge columns; only image-edge pads zeroed).

#define TS3 780   // row stride floats (3120B, 16B-multiple). data 8..771, pads 3 & 776.

__device__ __forceinline__ uint32_t smem_u32(const void* p)
{
    uint32_t a;
    asm("{ .reg .u64 t; cvta.to.shared.u64 t, %1; cvt.u32.u64 %0, t; }"
        : "=r"(a) : "l"(p));
    return a;
}

__device__ __forceinline__ void cp_async16(uint32_t dst, const float* src, bool valid)
{
    int sz = valid ? 16 : 0;
    asm volatile("cp.async.cg.shared.global [%0], [%1], 16, %2;"
                 :: "r"(dst), "l"(src), "r"(sz));
}

__device__ __forceinline__ float setge(float a, float b)
{
    float r;
    asm("set.ge.f32.f32 %0, %1, %2;" : "=f"(r) : "f"(a), "f"(b));
    return r;
}

// 9-slot histogram bucket address; slot = |fa - (signs_differ ? 8 : 0)| = fl mod 9
__device__ __forceinline__ uint32_t hog_class(float gx, float gy, uint32_t hb, float& mag)
{
    float d2 = fmaf(gx, gx, gy * gy);
    asm("sqrt.approx.f32 %0, %1;" : "=f"(mag) : "f"(d2));

    float u = fabsf(gx), v = fabsf(gy);
    float fa = (setge(u, 0.36397023f * v) + setge(u, 0.83909963f * v))
             + (setge(u, 1.73205081f * v) + setge(u, 5.67128182f * v));  // 0..4

    uint32_t xo = __float_as_uint(gx) ^ __float_as_uint(gy);
    float cf8 = ((int)xo < 0) ? 8.0f : 0.0f;
    float m = fabsf(fa - cf8) + 12582912.0f;     // 0x4B400000 + slot (exact)
    return hb + (__float_as_uint(m) << 10);
}

__device__ __forceinline__ void hog_pair(uint32_t a0, float m0, uint32_t a1, float m1)
{
    float msum = m0 + m1;
    asm volatile(
        "{\n\t"
        ".reg .pred p;\n\t"
        ".reg .f32 t0, t1, v0;\n\t"
        "setp.ne.u32 p, %0, %1;\n\t"
        "selp.f32 v0, %2, %3, p;\n\t"
        "ld.shared.f32 t0, [%0];\n\t"
        "@p ld.shared.f32 t1, [%1];\n\t"
        "add.f32 t0, t0, v0;\n\t"
        "@p add.f32 t1, t1, %4;\n\t"
        "st.shared.f32 [%0], t0;\n\t"
        "@p st.shared.f32 [%1], t1;\n\t"
        "}"
        :: "r"(a0), "r"(a1), "f"(m0), "f"(msum), "f"(m1));
}

__device__ __forceinline__ void emit(uint32_t hb, float gx0, float gy0, float gx1, float gy1)
{
    float m0, m1;
    uint32_t q0 = hog_class(gx0, gy0, hb, m0);
    uint32_t q1 = hog_class(gx1, gy1, hb, m1);
    hog_pair(q0, m0, q1, m1);
}

__global__ __launch_bounds__(256, 5)
void hog_kernel(const float* __restrict__ x, float* __restrict__ out)
{
    __shared__ __align__(16) float tile[10 * TS3];
    __shared__ float hist[9 * 256];

    const int tid = threadIdx.x;
    const int n   = blockIdx.x >> 6;
    const int cy  = blockIdx.x & 63;

#pragma unroll
    for (int b = 0; b < 9; ++b) hist[b * 256 + tid] = 0.0f;

    // ---- tile fill via cp.async: 1280 16B chunks; OOB rows zero-fill ----
    const float* img  = x + (size_t)n * (512 * 512);
    const int    row0 = cy * 8 - 1;
    const uint32_t tb = smem_u32(tile);
#pragma unroll
    for (int i = 0; i < 5; ++i) {
        int idx = tid + i * 256;          // 0..1279
        int r   = idx >> 7;               // tile row 0..9
        int k   = idx & 127;              // float4 chunk in row (cols 4k..4k+3)
        int gr  = row0 + r;
        bool ok = (unsigned)gr < 512u;
        const float* src = img + (size_t)(ok ? gr : 0) * 512 + k * 4;
        uint32_t dst = tb + (r * TS3 + 12 * (k >> 1) + (k & 1) * 4 + 8) * 4;
        cp_async16(dst, src, ok);
    }
    if (tid < 10) { tile[tid * TS3 + 3] = 0.f; tile[tid * TS3 + 776] = 0.f; }  // image edges
    asm volatile("cp.async.commit_group;" ::: "memory");
    asm volatile("cp.async.wait_group 0;" ::: "memory");
    __syncthreads();

    // ---- mainloop: thread = cell (8 cols) x 2 rows; 2 cols per step ----
    const int cell = tid >> 2;
    const int sub  = tid & 3;
    const float* pw = &tile[(2 * sub + 0) * TS3 + 12 * cell];
    const float* pa = &tile[(2 * sub + 1) * TS3 + 12 * cell];
    const float* pb = &tile[(2 * sub + 2) * TS3 + 12 * cell];
    const float* pc = &tile[(2 * sub + 3) * TS3 + 12 * cell];
    const uint32_t hb = smem_u32(&hist[tid]);

    float lw = pw[3], la = pa[3], lb = pb[3], lc = pc[3];   // col 8c-1 (neighbor data)
    float2 wp = *reinterpret_cast<const float2*>(pw + 8);
    float2 ap = *reinterpret_cast<const float2*>(pa + 8);
    float2 bp = *reinterpret_cast<const float2*>(pb + 8);
    float2 cp = *reinterpret_cast<const float2*>(pc + 8);

    float Am1 = lw + 2.f * la + lb;
    float Bm1 = la + 2.f * lb + lc;
    float A0 = wp.x + 2.f * ap.x + bp.x, A1 = wp.y + 2.f * ap.y + bp.y;
    float B0 = ap.x + 2.f * bp.x + cp.x, B1 = ap.y + 2.f * bp.y + cp.y;

    emit(hb,
         Am1 - A1, (lw + 2.f * wp.x + wp.y) - (lb + 2.f * bp.x + bp.y),
         Bm1 - B1, (la + 2.f * ap.x + ap.y) - (lc + 2.f * cp.x + cp.y));

    float w0 = wp.x, w1 = wp.y, a0 = ap.x, a1 = ap.y;
    float b0 = bp.x, b1 = bp.y, c0 = cp.x, c1 = cp.y;

#pragma unroll
    for (int k = 1; k < 4; ++k) {
        float2 wn = *reinterpret_cast<const float2*>(pw + 8 + 2 * k);
        float2 an = *reinterpret_cast<const float2*>(pa + 8 + 2 * k);
        float2 bn = *reinterpret_cast<const float2*>(pb + 8 + 2 * k);
        float2 cn = *reinterpret_cast<const float2*>(pc + 8 + 2 * k);
        float A2 = wn.x + 2.f * an.x + bn.x, A3 = wn.y + 2.f * an.y + bn.y;
        float B2 = an.x + 2.f * bn.x + cn.x, B3 = an.y + 2.f * bn.y + cn.y;

        emit(hb,
             A0 - A2, (w0 + 2.f * w1 + wn.x) - (b0 + 2.f * b1 + bn.x),
             B0 - B2, (a0 + 2.f * a1 + an.x) - (c0 + 2.f * c1 + cn.x));
        emit(hb,
             A1 - A3, (w1 + 2.f * wn.x + wn.y) - (b1 + 2.f * bn.x + bn.y),
             B1 - B3, (a1 + 2.f * an.x + an.y) - (c1 + 2.f * cn.x + cn.y));

        w0 = wn.x; w1 = wn.y; a0 = an.x; a1 = an.y;
        b0 = bn.x; b1 = bn.y; c0 = cn.x; c1 = cn.y;
        A0 = A2; A1 = A3; B0 = B2; B1 = B3;
    }

    // tail: col 7 with right halo col 8c+8 at [12c+20] (neighbor data / edge pad)
    {
        float rw = pw[20], ra = pa[20], rb = pb[20], rc = pc[20];
        float A8 = rw + 2.f * ra + rb;
        float B8 = ra + 2.f * rb + rc;
        emit(hb,
             A0 - A8, (w0 + 2.f * w1 + rw) - (b0 + 2.f * b1 + rb),
             B0 - B8, (a0 + 2.f * a1 + ra) - (c0 + 2.f * c1 + rc));
    }

    asm volatile("" ::: "memory");   // order fold reads after asm RMWs

    // ---- fold: bin[b] = P9[b] + P9[(b+8)%9]; shuffle-reduce 4 subs; write ----
    float P[9];
#pragma unroll
    for (int s = 0; s < 9; ++s) P[s] = hist[s * 256 + tid];
    float bin[9];
#pragma unroll
    for (int b = 0; b < 9; ++b) bin[b] = P[b] + P[(b + 8) % 9];

#pragma unroll
    for (int b = 0; b < 9; ++b) {
        bin[b] += __shfl_xor_sync(0xffffffffu, bin[b], 1);
        bin[b] += __shfl_xor_sync(0xffffffffu, bin[b], 2);
    }

    if (sub == 0) {
        float* o = out + (size_t)n * 36864 + cy * 64 + cell;
#pragma unroll
        for (int b = 0; b < 9; ++b)
            o[(size_t)b * 4096] = bin[b] * 0.015625f;   // 1/64
    }
}

extern "C" void kernel_launch(void* const* d_in, const int* in_sizes, int n_in,
                              void* d_out, int out_size)
{
    const float* x = (const float*)d_in[0];
    float* out = (float*)d_out;
    (void)in_sizes; (void)n_in; (void)out_size;
    hog_kernel<<<4096, 256>>>(x, out);
}

// round 13
// speedup vs baseline: 1.0693x; 1.0067x over previous
#include <cuda_runtime.h>
#include <cstdint>

// HOG fused kernel R13: R9 body (stride-10 float2 tile, 9-slot mod-9 histogram,
// paired overlapped RMW) with 6-blocks/SM launch bound (48 warps/SM).
// x: (64,1,512,512) f32. out: (64, 9*64*64) f32.
// Block = (image n, cell-row cy) stripe, 256 threads: cell = t/4, sub = t%4 (2 rows).
// Tile: col c -> 10*(c>>3) + (c&7) + 4; halos shared with neighbor cells
// (left halo of cell c = idx 10c+1, right halo = idx 10c+14); edge pads idx 1/644.

#define TS2 646

__device__ __forceinline__ uint32_t smem_u32(const void* p)
{
    uint32_t a;
    asm("{ .reg .u64 t; cvta.to.shared.u64 t, %1; cvt.u32.u64 %0, t; }"
        : "=r"(a) : "l"(p));
    return a;
}

__device__ __forceinline__ float setge(float a, float b)
{
    float r;
    asm("set.ge.f32.f32 %0, %1, %2;" : "=f"(r) : "f"(a), "f"(b));
    return r;
}

// 9-slot histogram bucket address; slot = |fa - (signs_differ ? 8 : 0)| = fl mod 9
__device__ __forceinline__ uint32_t hog_class(float gx, float gy, uint32_t hb, float& mag)
{
    float d2 = fmaf(gx, gx, gy * gy);
    asm("sqrt.approx.f32 %0, %1;" : "=f"(mag) : "f"(d2));

    float u = fabsf(gx), v = fabsf(gy);
    float fa = (setge(u, 0.36397023f * v) + setge(u, 0.83909963f * v))
             + (setge(u, 1.73205081f * v) + setge(u, 5.67128182f * v));  // 0..4

    uint32_t xo = __float_as_uint(gx) ^ __float_as_uint(gy);
    float cf8 = ((int)xo < 0) ? 8.0f : 0.0f;
    float m = fabsf(fa - cf8) + 12582912.0f;     // 0x4B400000 + slot (exact)
    return hb + (__float_as_uint(m) << 10);
}

__device__ __forceinline__ void hog_pair(uint32_t a0, float m0, uint32_t a1, float m1)
{
    float msum = m0 + m1;
    asm volatile(
        "{\n\t"
        ".reg .pred p;\n\t"
        ".reg .f32 t0, t1, v0;\n\t"
        "setp.ne.u32 p, %0, %1;\n\t"
        "selp.f32 v0, %2, %3, p;\n\t"
        "ld.shared.f32 t0, [%0];\n\t"
        "@p ld.shared.f32 t1, [%1];\n\t"
        "add.f32 t0, t0, v0;\n\t"
        "@p add.f32 t1, t1, %4;\n\t"
        "st.shared.f32 [%0], t0;\n\t"
        "@p st.shared.f32 [%1], t1;\n\t"
        "}"
        :: "r"(a0), "r"(a1), "f"(m0), "f"(msum), "f"(m1));
}

__device__ __forceinline__ void emit(uint32_t hb, float gx0, float gy0, float gx1, float gy1)
{
    float m0, m1;
    uint32_t q0 = hog_class(gx0, gy0, hb, m0);
    uint32_t q1 = hog_class(gx1, gy1, hb, m1);
    hog_pair(q0, m0, q1, m1);
}

__global__ __launch_bounds__(256, 6)
void hog_kernel(const float* __restrict__ x, float* __restrict__ out)
{
    __shared__ __align__(16) float tile[10 * TS2];
    __shared__ float hist[9 * 256];

    const int tid = threadIdx.x;
    const int n   = blockIdx.x >> 6;
    const int cy  = blockIdx.x & 63;

#pragma unroll
    for (int b = 0; b < 9; ++b) hist[b * 256 + tid] = 0.0f;

    // ---- load 10 rows into padded tile ----
    const float* img  = x + (size_t)n * (512 * 512);
    const int    row0 = cy * 8 - 1;
#pragma unroll
    for (int i = 0; i < 5; ++i) {
        int idx = tid + i * 256;
        int r   = idx >> 7;
        int k   = idx & 127;
        int gr  = row0 + r;
        float4 v = make_float4(0.f, 0.f, 0.f, 0.f);
        if ((unsigned)gr < 512u)
            v = *reinterpret_cast<const float4*>(img + (size_t)gr * 512 + k * 4);
        float* d = &tile[r * TS2 + 5 * k + 4 - (k & 1)];
        *reinterpret_cast<float2*>(d)     = make_float2(v.x, v.y);
        *reinterpret_cast<float2*>(d + 2) = make_float2(v.z, v.w);
    }
    if (tid < 10) { tile[tid * TS2 + 1] = 0.f; tile[tid * TS2 + 644] = 0.f; }
    __syncthreads();

    // ---- mainloop: thread = cell (8 cols) x 2 rows; 2 cols per step ----
    const int cell = tid >> 2;
    const int sub  = tid & 3;
    const float* pw = &tile[(2 * sub + 0) * TS2 + 10 * cell];
    const float* pa = &tile[(2 * sub + 1) * TS2 + 10 * cell];
    const float* pb = &tile[(2 * sub + 2) * TS2 + 10 * cell];
    const float* pc = &tile[(2 * sub + 3) * TS2 + 10 * cell];
    const uint32_t hb = smem_u32(&hist[tid]);

    float lw = pw[1], la = pa[1], lb = pb[1], lc = pc[1];   // col 8c-1
    float2 wp = *reinterpret_cast<const float2*>(pw + 4);
    float2 ap = *reinterpret_cast<const float2*>(pa + 4);
    float2 bp = *reinterpret_cast<const float2*>(pb + 4);
    float2 cp = *reinterpret_cast<const float2*>(pc + 4);

    float Am1 = lw + 2.f * la + lb;
    float Bm1 = la + 2.f * lb + lc;
    float A0 = wp.x + 2.f * ap.x + bp.x, A1 = wp.y + 2.f * ap.y + bp.y;
    float B0 = ap.x + 2.f * bp.x + cp.x, B1 = ap.y + 2.f * bp.y + cp.y;

    emit(hb,
         Am1 - A1, (lw + 2.f * wp.x + wp.y) - (lb + 2.f * bp.x + bp.y),
         Bm1 - B1, (la + 2.f * ap.x + ap.y) - (lc + 2.f * cp.x + cp.y));

    float w0 = wp.x, w1 = wp.y, a0 = ap.x, a1 = ap.y;
    float b0 = bp.x, b1 = bp.y, c0 = cp.x, c1 = cp.y;

#pragma unroll
    for (int k = 1; k < 4; ++k) {
        float2 wn = *reinterpret_cast<const float2*>(pw + 4 + 2 * k);
        float2 an = *reinterpret_cast<const float2*>(pa + 4 + 2 * k);
        float2 bn = *reinterpret_cast<const float2*>(pb + 4 + 2 * k);
        float2 cn = *reinterpret_cast<const float2*>(pc + 4 + 2 * k);
        float A2 = wn.x + 2.f * an.x + bn.x, A3 = wn.y + 2.f * an.y + bn.y;
        float B2 = an.x + 2.f * bn.x + cn.x, B3 = an.y + 2.f * bn.y + cn.y;

        emit(hb,
             A0 - A2, (w0 + 2.f * w1 + wn.x) - (b0 + 2.f * b1 + bn.x),
             B0 - B2, (a0 + 2.f * a1 + an.x) - (c0 + 2.f * c1 + cn.x));
        emit(hb,
             A1 - A3, (w1 + 2.f * wn.x + wn.y) - (b1 + 2.f * bn.x + bn.y),
             B1 - B3, (a1 + 2.f * an.x + an.y) - (c1 + 2.f * cn.x + cn.y));

        w0 = wn.x; w1 = wn.y; a0 = an.x; a1 = an.y;
        b0 = bn.x; b1 = bn.y; c0 = cn.x; c1 = cn.y;
        A0 = A2; A1 = A3; B0 = B2; B1 = B3;
    }

    // tail: col 7 with right halo col 8 (idx 10c+14)
    {
        float rw = pw[14], ra = pa[14], rb = pb[14], rc = pc[14];
        float A8 = rw + 2.f * ra + rb;
        float B8 = ra + 2.f * rb + rc;
        emit(hb,
             A0 - A8, (w0 + 2.f * w1 + rw) - (b0 + 2.f * b1 + rb),
             B0 - B8, (a0 + 2.f * a1 + ra) - (c0 + 2.f * c1 + rc));
    }

    asm volatile("" ::: "memory");   // order fold reads after asm RMWs

    // ---- fold: bin[b] = P9[b] + P9[(b+8)%9]; shuffle-reduce 4 subs; write ----
    float P[9];
#pragma unroll
    for (int s = 0; s < 9; ++s) P[s] = hist[s * 256 + tid];
    float bin[9];
#pragma unroll
    for (int b = 0; b < 9; ++b) bin[b] = P[b] + P[(b + 8) % 9];

#pragma unroll
    for (int b = 0; b < 9; ++b) {
        bin[b] += __shfl_xor_sync(0xffffffffu, bin[b], 1);
        bin[b] += __shfl_xor_sync(0xffffffffu, bin[b], 2);
    }

    if (sub == 0) {
        float* o = out + (size_t)n * 36864 + cy * 64 + cell;
#pragma unroll
        for (int b = 0; b < 9; ++b)
            o[(size_t)b * 4096] = bin[b] * 0.015625f;   // 1/64
    }
}

extern "C" void kernel_launch(void* const* d_in, const int* in_sizes, int n_in,
                              void* d_out, int out_size)
{
    const float* x = (const float*)d_in[0];
    float* out = (float*)d_out;
    (void)in_sizes; (void)n_in; (void)out_size;
    hog_kernel<<<4096, 256>>>(x, out);
}